// round 12
// baseline (speedup 1.0000x reference)
#include <cuda_runtime.h>
#include <cuda_fp16.h>

#define N_NODES 50000
#define N_EDGES 1600000
#define N_GRAPHS 256
#define HID 128
#define NB 196    // ceil(N_NODES/256)
#define GB 782    // ceil(N_NODES/64)   (GEMM blocks)
#define EB2 3125  // N_EDGES/2/256      (hist/fill blocks, 2 edges/thread)

// ---------------- scratch (static device globals; no runtime alloc) --------
// Zero-initialized at module load. Kernels restore the zero invariant for
// g_degcnt / g_emb / g_gcnt after consuming them, so every call sees zeros.
__device__ __half2 g_bufH[(size_t)N_NODES * HID / 2];  // fp16 h@W (GEMM out)
__device__ __half2 g_bufX[(size_t)N_NODES * HID / 2];  // fp16 node features
__device__ int   g_src[N_EDGES];
__device__ int   g_dst[N_EDGES];
__device__ unsigned short g_rank[N_EDGES];   // edge rank within its dst row
__device__ int2  g_csr[N_EDGES];             // interleaved (src, coef-as-bits)
__device__ unsigned long long g_degcnt[N_NODES]; // cnt<<44 | deg(fixed 2^-24)
__device__ int   g_cnt[N_NODES];
__device__ int   g_rowptr[N_NODES + 1];
__device__ int   g_batch[N_NODES];
__device__ float g_dinv[N_NODES];
__device__ float g_self[N_NODES];
__device__ float g_emb[N_GRAPHS * HID];
__device__ float g_gcnt[N_GRAPHS];
__device__ int   g_bsum[256];

// ---------------- MMA helpers ------------------------------------------------
__device__ __forceinline__ void ldsm_x4(unsigned& r0, unsigned& r1,
                                        unsigned& r2, unsigned& r3, unsigned a) {
    asm volatile("ldmatrix.sync.aligned.m8n8.x4.shared.b16 {%0,%1,%2,%3}, [%4];"
                 : "=r"(r0), "=r"(r1), "=r"(r2), "=r"(r3) : "r"(a));
}
__device__ __forceinline__ void ldsm_x4t(unsigned& r0, unsigned& r1,
                                         unsigned& r2, unsigned& r3, unsigned a) {
    asm volatile("ldmatrix.sync.aligned.m8n8.x4.trans.shared.b16 {%0,%1,%2,%3}, [%4];"
                 : "=r"(r0), "=r"(r1), "=r"(r2), "=r"(r3) : "r"(a));
}
__device__ __forceinline__ void mma16816(float* c, const unsigned* a,
                                         const unsigned* b) {
    asm volatile("mma.sync.aligned.m16n8k16.row.col.f32.f16.f16.f32 "
                 "{%0,%1,%2,%3}, {%4,%5,%6,%7}, {%8,%9}, {%0,%1,%2,%3};"
                 : "+f"(c[0]), "+f"(c[1]), "+f"(c[2]), "+f"(c[3])
                 : "r"(a[0]), "r"(a[1]), "r"(a[2]), "r"(a[3]),
                   "r"(b[0]), "r"(b[1]));
}

// GEMM mainloop body; smem tiles populated; stores fp16 C for 64 rows at m0.
__device__ __forceinline__ void gemm_compute(unsigned char* s_a,
                                             unsigned char* s_w,
                                             __half2* __restrict__ C,
                                             int M, int m0, int tid) {
    const int lane = tid & 31;
    const int wid = tid >> 5;
    const int wm = wid >> 2, wn = wid & 3;
    unsigned sa = (unsigned)__cvta_generic_to_shared(s_a);
    unsigned sw = (unsigned)__cvta_generic_to_shared(s_w);

    float acc[2][4][4];
#pragma unroll
    for (int mt = 0; mt < 2; mt++)
#pragma unroll
        for (int nt = 0; nt < 4; nt++)
#pragma unroll
            for (int j = 0; j < 4; j++) acc[mt][nt][j] = 0.0f;

    const int a_r0 = wm * 32 + (lane & 15);
    const int a_kh = (lane >> 4) * 8;
    const int b_kr = (lane & 7) + ((lane >> 3) & 1) * 8;
    const int b_n0 = wn * 32 + (lane >> 4) * 8;

#pragma unroll
    for (int ks = 0; ks < 8; ks++) {
        unsigned a[2][4], b[4][2];
#pragma unroll
        for (int mt = 0; mt < 2; mt++) {
            int row = a_r0 + mt * 16;
            unsigned byte = (unsigned)(row * 256 + (ks * 16 + a_kh) * 2);
            unsigned ad = sa + (byte ^ ((unsigned)(row & 7) << 4));
            ldsm_x4(a[mt][0], a[mt][1], a[mt][2], a[mt][3], ad);
        }
#pragma unroll
        for (int p = 0; p < 2; p++) {
            int k = ks * 16 + b_kr;
            unsigned byte = (unsigned)(k * 256 + (b_n0 + p * 16) * 2);
            unsigned ad = sw + (byte ^ ((unsigned)(k & 7) << 4));
            ldsm_x4t(b[2 * p][0], b[2 * p][1], b[2 * p + 1][0], b[2 * p + 1][1], ad);
        }
#pragma unroll
        for (int mt = 0; mt < 2; mt++)
#pragma unroll
            for (int nt = 0; nt < 4; nt++)
                mma16816(acc[mt][nt], a[mt], b[nt]);
    }

#pragma unroll
    for (int mt = 0; mt < 2; mt++) {
        int r0 = m0 + wm * 32 + mt * 16 + (lane >> 2);
#pragma unroll
        for (int nt = 0; nt < 4; nt++) {
            int ci = wn * 16 + nt * 4 + (lane & 3);
            if (r0 < M)
                C[(size_t)r0 * 64 + ci] = __floats2half2_rn(acc[mt][nt][0], acc[mt][nt][1]);
            if (r0 + 8 < M)
                C[(size_t)(r0 + 8) * 64 + ci] = __floats2half2_rn(acc[mt][nt][2], acc[mt][nt][3]);
        }
    }
}

__device__ __forceinline__ void load_w_tile(unsigned char* s_w,
                                            const float* __restrict__ W, int tid) {
#pragma unroll
    for (int i = 0; i < 16; i++) {
        int f = i * 256 + tid;
        int r = f >> 5, c4 = f & 31;
        float4 v = *(const float4*)&W[(size_t)r * 128 + c4 * 4];
        __half2 h0 = __floats2half2_rn(v.x, v.y);
        __half2 h1 = __floats2half2_rn(v.z, v.w);
        unsigned byte = (unsigned)(r * 256 + c4 * 8);
        unsigned swb = byte ^ ((unsigned)(r & 7) << 4);
        uint2 u = make_uint2(*(unsigned*)&h0, *(unsigned*)&h1);
        *(uint2*)(s_w + swb) = u;
    }
}

// ---------------- fused: layer-1 GEMM  ||  edge histogram / conversion ------
__global__ void __launch_bounds__(256) k_gemm1_hist(
    const float* __restrict__ x, const float* __restrict__ W1,
    __half2* __restrict__ C,
    const void* ei, const void* batch, const float* __restrict__ ew) {
    __shared__ __align__(16) unsigned char s_a[64 * 256];   // 16 KB
    __shared__ __align__(16) unsigned char s_w[128 * 256];  // 32 KB
    const int tid = threadIdx.x;

    if (blockIdx.x < GB) {
        const int m0 = blockIdx.x * 64;
#pragma unroll
        for (int i = 0; i < 8; i++) {
            int f = i * 256 + tid;
            int r = f >> 5, c4 = f & 31;
            int gm = m0 + r;
            float4 v = make_float4(0.f, 0.f, 0.f, 0.f);
            if (gm < N_NODES) v = *(const float4*)&x[(size_t)gm * 128 + c4 * 4];
            __half2 h0 = __floats2half2_rn(v.x, v.y);
            __half2 h1 = __floats2half2_rn(v.z, v.w);
            unsigned byte = (unsigned)(r * 256 + c4 * 8);
            unsigned swb = byte ^ ((unsigned)(r & 7) << 4);
            uint2 u = make_uint2(*(unsigned*)&h0, *(unsigned*)&h1);
            *(uint2*)(s_a + swb) = u;
        }
        load_w_tile(s_w, W1, tid);
        __syncthreads();
        gemm_compute(s_a, s_w, C, N_NODES, m0, tid);
        return;
    }

    // ---- histogram branch ----
    const unsigned* u32 = (const unsigned*)ei;
    int is64 = 1;
#pragma unroll
    for (int i = 1; i < 16; i += 2)
        if (u32[i] != 0u) is64 = 0;

    int t = (blockIdx.x - GB) * 256 + tid;
    int e0 = t * 2;
    if (e0 < N_EDGES) {
        int s0, s1, d0, d1;
        if (is64) {
            const longlong2* p = (const longlong2*)ei;
            longlong2 vs = __ldg(&p[t]);
            longlong2 vd = __ldg(&p[N_EDGES / 2 + t]);
            s0 = (int)vs.x; s1 = (int)vs.y;
            d0 = (int)vd.x; d1 = (int)vd.y;
        } else {
            const int2* p = (const int2*)ei;
            int2 vs = __ldg(&p[t]);
            int2 vd = __ldg(&p[N_EDGES / 2 + t]);
            s0 = vs.x; s1 = vs.y;
            d0 = vd.x; d1 = vd.y;
        }
        float2 w = __ldg(&((const float2*)ew)[t]);
        *(int2*)&g_src[e0] = make_int2(s0, s1);
        *(int2*)&g_dst[e0] = make_int2(d0, d1);
        unsigned long long f0 =
            (1ull << 44) | (unsigned long long)__float2uint_rn(w.x * 16777216.0f);
        unsigned long long f1 =
            (1ull << 44) | (unsigned long long)__float2uint_rn(w.y * 16777216.0f);
        unsigned long long o0 = atomicAdd(&g_degcnt[d0], f0);
        unsigned long long o1 = atomicAdd(&g_degcnt[d1], f1);
        g_rank[e0 + 0] = (unsigned short)(o0 >> 44);
        g_rank[e0 + 1] = (unsigned short)(o1 >> 44);
    }
    if (t < N_NODES) {
        int b = is64 ? (int)((const long long*)batch)[t]
                     : ((const int*)batch)[t];
        g_batch[t] = b;
        atomicAdd(&g_gcnt[b], 1.0f);
    }
}

// ---- 2-stage scan: unpack (cnt,deg) (+re-zero degcnt), sums, then scan -----
__global__ void __launch_bounds__(256) k_scan1() {
    __shared__ int ws[8];
    int tid = threadIdx.x;
    int t = blockIdx.x * 256 + tid;
    int c = 0;
    if (t < N_NODES) {
        unsigned long long p = g_degcnt[t];
        g_degcnt[t] = 0ull;   // restore zero invariant for next call
        c = (int)(p >> 44);
        float deg = (float)(p & ((1ull << 44) - 1ull)) * (1.0f / 16777216.0f)
                    + 1.0f;   // + self-loop
        float r = rsqrtf(deg);
        g_dinv[t] = r;
        g_self[t] = r * r;
        g_cnt[t] = c;
    }
    int v = c;
#pragma unroll
    for (int off = 16; off; off >>= 1)
        v += __shfl_down_sync(0xffffffffu, v, off);
    if ((tid & 31) == 0) ws[tid >> 5] = v;
    __syncthreads();
    if (tid == 0) {
        int s = 0;
#pragma unroll
        for (int i = 0; i < 8; i++) s += ws[i];
        g_bsum[blockIdx.x] = s;
    }
}

__global__ void __launch_bounds__(256) k_scan2() {
    __shared__ int sb[256];
    __shared__ int sh[256];
    int tid = threadIdx.x;
    int bv = (tid < NB) ? g_bsum[tid] : 0;
    sb[tid] = bv;
    __syncthreads();
#pragma unroll
    for (int off = 1; off < 256; off <<= 1) {
        int u = (tid >= off) ? sb[tid - off] : 0;
        __syncthreads();
        sb[tid] += u;
        __syncthreads();
    }
    int base = (blockIdx.x > 0) ? sb[blockIdx.x - 1] : 0;

    int t = blockIdx.x * 256 + tid;
    int c = (t < N_NODES) ? g_cnt[t] : 0;
    sh[tid] = c;
    __syncthreads();
#pragma unroll
    for (int off = 1; off < 256; off <<= 1) {
        int u = (tid >= off) ? sh[tid - off] : 0;
        __syncthreads();
        sh[tid] += u;
        __syncthreads();
    }
    if (t < N_NODES) {
        g_rowptr[t] = base + sh[tid] - c;
        if (t == N_NODES - 1) g_rowptr[N_NODES] = base + sh[tid];
    }
}

// fill CSR: atomic-free, ONE 8B scattered store per edge (interleaved pair).
__global__ void k_fill(const float* __restrict__ ew) {
    int t = blockIdx.x * blockDim.x + threadIdx.x;
    int e0 = t * 2;
    if (e0 >= N_EDGES) return;
    int2 s = *(const int2*)&g_src[e0];
    int2 d = *(const int2*)&g_dst[e0];
    float2 w = __ldg(&((const float2*)ew)[t]);
    int r0 = (int)g_rank[e0 + 0];
    int r1 = (int)g_rank[e0 + 1];
    int p0 = __ldg(&g_rowptr[d.x]) + r0;
    int p1 = __ldg(&g_rowptr[d.y]) + r1;
    float c0 = g_dinv[s.x] * g_dinv[d.x] * w.x;
    float c1 = g_dinv[s.y] * g_dinv[d.y] * w.y;
    g_csr[p0] = make_int2(s.x, __float_as_int(c0));
    g_csr[p1] = make_int2(s.y, __float_as_int(c1));
}

// ---------------- GEMM for fp16 input (layers 2/3, relu fused on load) ------
__global__ void __launch_bounds__(256) k_gemm_h(const uint4* __restrict__ A,
                                                const float* __restrict__ W,
                                                __half2* __restrict__ C) {
    __shared__ __align__(16) unsigned char s_a[64 * 256];   // 16 KB
    __shared__ __align__(16) unsigned char s_w[128 * 256];  // 32 KB
    const int tid = threadIdx.x;
    const int m0 = blockIdx.x * 64;

#pragma unroll
    for (int i = 0; i < 4; i++) {
        int f = i * 256 + tid;
        int r = f >> 4, u = f & 15;
        int gm = m0 + r;
        uint4 v = make_uint4(0u, 0u, 0u, 0u);
        if (gm < N_NODES) v = __ldg(&A[(size_t)gm * 16 + u]);
        __half2 z = __float2half2_rn(0.0f);
        *(__half2*)&v.x = __hmax2(*(__half2*)&v.x, z);
        *(__half2*)&v.y = __hmax2(*(__half2*)&v.y, z);
        *(__half2*)&v.z = __hmax2(*(__half2*)&v.z, z);
        *(__half2*)&v.w = __hmax2(*(__half2*)&v.w, z);
        unsigned byte = (unsigned)(r * 256 + u * 16);
        unsigned swb = byte ^ ((unsigned)(r & 7) << 4);
        *(uint4*)(s_a + swb) = v;
    }
    load_w_tile(s_w, W, tid);
    __syncthreads();
    gemm_compute(s_a, s_w, C, N_NODES, m0, tid);
}

// ---------------- aggregate: b + self[n]*hw[n] + sum coef*hw[src] ----------
// Interleaved (src,coef) 8B edge loads, fp16 feature gather (256B/row),
// fp32 accumulate, 4-wide interleaved scalar MLP. One warp per node.
__device__ __forceinline__ float4 agg_node(const uint2* __restrict__ hw4,
                                           const float* __restrict__ bias,
                                           int node, int lane) {
    int r0 = __ldg(&g_rowptr[node]);
    int r1 = __ldg(&g_rowptr[node + 1]);

    float4 b = *(const float4*)&bias[lane * 4];
    float  s = g_self[node];
    uint2 uself = __ldg(&hw4[(size_t)node * 32 + lane]);
    float2 s0 = __half22float2(*(__half2*)&uself.x);
    float2 s1 = __half22float2(*(__half2*)&uself.y);
    float4 a0 = make_float4(b.x + s * s0.x, b.y + s * s0.y,
                            b.z + s * s1.x, b.w + s * s1.y);
    float4 a1 = make_float4(0.f, 0.f, 0.f, 0.f);
    float4 a2 = a1, a3 = a1;

    int e = r0;
    for (; e + 4 <= r1; e += 4) {
        int2 w0 = __ldg(&g_csr[e + 0]);
        int2 w1 = __ldg(&g_csr[e + 1]);
        int2 w2 = __ldg(&g_csr[e + 2]);
        int2 w3 = __ldg(&g_csr[e + 3]);
        float c0 = __int_as_float(w0.y);
        float c1 = __int_as_float(w1.y);
        float c2 = __int_as_float(w2.y);
        float c3 = __int_as_float(w3.y);
        uint2 u0 = __ldg(&hw4[(size_t)w0.x * 32 + lane]);
        uint2 u1 = __ldg(&hw4[(size_t)w1.x * 32 + lane]);
        uint2 u2 = __ldg(&hw4[(size_t)w2.x * 32 + lane]);
        uint2 u3 = __ldg(&hw4[(size_t)w3.x * 32 + lane]);
        float2 p, q;
        p = __half22float2(*(__half2*)&u0.x); q = __half22float2(*(__half2*)&u0.y);
        a0.x += c0 * p.x; a0.y += c0 * p.y; a0.z += c0 * q.x; a0.w += c0 * q.y;
        p = __half22float2(*(__half2*)&u1.x); q = __half22float2(*(__half2*)&u1.y);
        a1.x += c1 * p.x; a1.y += c1 * p.y; a1.z += c1 * q.x; a1.w += c1 * q.y;
        p = __half22float2(*(__half2*)&u2.x); q = __half22float2(*(__half2*)&u2.y);
        a2.x += c2 * p.x; a2.y += c2 * p.y; a2.z += c2 * q.x; a2.w += c2 * q.y;
        p = __half22float2(*(__half2*)&u3.x); q = __half22float2(*(__half2*)&u3.y);
        a3.x += c3 * p.x; a3.y += c3 * p.y; a3.z += c3 * q.x; a3.w += c3 * q.y;
    }
    for (; e < r1; e++) {
        int2 w0 = __ldg(&g_csr[e]);
        float c0 = __int_as_float(w0.y);
        uint2 u0 = __ldg(&hw4[(size_t)w0.x * 32 + lane]);
        float2 p = __half22float2(*(__half2*)&u0.x);
        float2 q = __half22float2(*(__half2*)&u0.y);
        a0.x += c0 * p.x; a0.y += c0 * p.y; a0.z += c0 * q.x; a0.w += c0 * q.y;
    }
    return make_float4(a0.x + a1.x + a2.x + a3.x,
                       a0.y + a1.y + a2.y + a3.y,
                       a0.z + a1.z + a2.z + a3.z,
                       a0.w + a1.w + a2.w + a3.w);
}

// layers 1-2: store raw (pre-relu) fp16 features; next GEMM applies relu.
__global__ void __launch_bounds__(256) k_aggregate_h(const __half2* __restrict__ hw,
                                                     const float* __restrict__ bias,
                                                     uint2* __restrict__ out) {
    int node = (blockIdx.x * 256 + threadIdx.x) >> 5;
    int lane = threadIdx.x & 31;
    if (node >= N_NODES) return;
    float4 o = agg_node((const uint2*)hw, bias, node, lane);
    uint2 r;
    __half2 h0 = __floats2half2_rn(o.x, o.y);
    __half2 h1 = __floats2half2_rn(o.z, o.w);
    r.x = *(unsigned*)&h0;
    r.y = *(unsigned*)&h1;
    out[(size_t)node * 32 + lane] = r;
}

// layer-3 aggregate fused with mean-pool accumulation
__global__ void __launch_bounds__(256) k_aggregate_pool(const __half2* __restrict__ hw,
                                                        const float* __restrict__ bias) {
    int node = (blockIdx.x * 256 + threadIdx.x) >> 5;
    int lane = threadIdx.x & 31;
    if (node >= N_NODES) return;
    float4 o = agg_node((const uint2*)hw, bias, node, lane);
    int g = g_batch[node];
    float* p = &g_emb[g * 128 + lane * 4];
    asm volatile("red.global.add.v4.f32 [%0], {%1, %2, %3, %4};"
                 :: "l"(p), "f"(o.x), "f"(o.y), "f"(o.z), "f"(o.w)
                 : "memory");
}

// ---------------- classifier (re-zeros emb/gcnt after use) ------------------
__global__ void k_classify(const float* __restrict__ lw1,
                           const float* __restrict__ lb1,
                           const float* __restrict__ lw2,
                           const float* __restrict__ lb2,
                           float* __restrict__ out) {
    int lane = threadIdx.x & 31;
    int g = (blockIdx.x * blockDim.x + threadIdx.x) >> 5;
    if (g >= N_GRAPHS) return;
    float inv = 1.0f / fmaxf(g_gcnt[g], 1.0f);
    float e[4];
#pragma unroll
    for (int j = 0; j < 4; j++) {
        e[j] = g_emb[g * 128 + lane + 32 * j] * inv;
        g_emb[g * 128 + lane + 32 * j] = 0.0f;   // restore zero invariant
    }
    if (lane == 0) g_gcnt[g] = 0.0f;             // restore zero invariant
    float t[4] = {lb1[lane], lb1[lane + 32], lb1[lane + 64], lb1[lane + 96]};
#pragma unroll
    for (int k0 = 0; k0 < 4; k0++) {
#pragma unroll
        for (int kk = 0; kk < 32; kk++) {
            float a = __shfl_sync(0xffffffffu, e[k0], kk);
            int k = k0 * 32 + kk;
            t[0] += a * lw1[k * 128 + lane];
            t[1] += a * lw1[k * 128 + lane + 32];
            t[2] += a * lw1[k * 128 + lane + 64];
            t[3] += a * lw1[k * 128 + lane + 96];
        }
    }
#pragma unroll
    for (int o = 0; o < 10; o++) {
        float p = t[0] * lw2[lane * 10 + o] + t[1] * lw2[(lane + 32) * 10 + o] +
                  t[2] * lw2[(lane + 64) * 10 + o] + t[3] * lw2[(lane + 96) * 10 + o];
#pragma unroll
        for (int off = 16; off; off >>= 1)
            p += __shfl_down_sync(0xffffffffu, p, off);
        if (lane == 0) out[g * 10 + o] = p + lb2[o];
    }
}

// ---------------- launch ----------------------------------------------------
extern "C" void kernel_launch(void* const* d_in, const int* in_sizes, int n_in,
                              void* d_out, int out_size) {
    const float* x   = (const float*)d_in[0];
    const void*  ei  = d_in[1];
    const float* ew  = (const float*)d_in[2];
    const void*  bt  = d_in[3];
    const float* W1  = (const float*)d_in[4];
    const float* b1  = (const float*)d_in[5];
    const float* W2  = (const float*)d_in[6];
    const float* b2  = (const float*)d_in[7];
    const float* W3  = (const float*)d_in[8];
    const float* b3  = (const float*)d_in[9];
    const float* lw1 = (const float*)d_in[10];
    const float* lb1 = (const float*)d_in[11];
    const float* lw2 = (const float*)d_in[12];
    const float* lb2 = (const float*)d_in[13];
    float* out = (float*)d_out;

    __half2 *bufH, *bufX;
    cudaGetSymbolAddress((void**)&bufH, g_bufH);
    cudaGetSymbolAddress((void**)&bufX, g_bufX);

    const int AB = (N_NODES * 32 + 255) / 256;   // 6250 (warp per node)

    // ---- fused layer-1 GEMM || edge histogram; then CSR build ----
    k_gemm1_hist<<<GB + EB2, 256>>>(x, W1, bufH, ei, bt, ew);
    k_scan1<<<NB, 256>>>();
    k_scan2<<<NB, 256>>>();
    k_fill<<<EB2, 256>>>(ew);

    // ---- layer 1 aggregate -> X (fp16, pre-relu) ----
    k_aggregate_h<<<AB, 256>>>(bufH, b1, (uint2*)bufX);
    // ---- layer 2: relu(X) fp16 -> H; aggregate -> X ----
    k_gemm_h<<<GB, 256>>>((const uint4*)bufX, W2, bufH);
    k_aggregate_h<<<AB, 256>>>(bufH, b2, (uint2*)bufX);
    // ---- layer 3: relu(X) fp16 -> H; aggregate + pool fused ----
    k_gemm_h<<<GB, 256>>>((const uint4*)bufX, W3, bufH);
    k_aggregate_pool<<<AB, 256>>>(bufH, b3);

    // ---- classify ----
    k_classify<<<(N_GRAPHS * 32 + 255) / 256, 256>>>(lw1, lb1, lw2, lb2, out);
}

// round 13
// speedup vs baseline: 1.0808x; 1.0808x over previous
#include <cuda_runtime.h>
#include <cuda_fp16.h>

#define N_NODES 50000
#define N_EDGES 1600000
#define N_GRAPHS 256
#define HID 128
#define NB 196    // ceil(N_NODES/256)
#define GB 782    // ceil(N_NODES/64)   (GEMM blocks)
#define EB2 3125  // N_EDGES/2/256      (hist/fill blocks, 2 edges/thread)

// ---------------- scratch (static device globals; no runtime alloc) --------
// Zero-initialized at module load. Kernels restore the zero invariant for
// g_degcnt / g_emb / g_gcnt after consuming them, so every call sees zeros.
__device__ __half2 g_bufH[(size_t)N_NODES * HID / 2];  // fp16 h@W (GEMM out)
__device__ __half2 g_bufX[(size_t)N_NODES * HID / 2];  // fp16 node features
__device__ int   g_src[N_EDGES];
__device__ int   g_dst[N_EDGES];
__device__ unsigned short g_rank[N_EDGES];   // edge rank within its dst row
__device__ int   g_csr_src[N_EDGES];         // separate arrays: measured-best
__device__ float g_csr_coef[N_EDGES];        // holds dinv[src]*w (dst factored)
__device__ unsigned long long g_degcnt[N_NODES]; // cnt<<44 | deg(fixed 2^-24)
__device__ int   g_cnt[N_NODES];
__device__ int   g_rowptr[N_NODES + 1];
__device__ int   g_batch[N_NODES];
__device__ float g_dinv[N_NODES];
__device__ float g_self[N_NODES];
__device__ float g_emb[N_GRAPHS * HID];
__device__ float g_gcnt[N_GRAPHS];
__device__ int   g_bsum[256];

// ---------------- MMA helpers ------------------------------------------------
__device__ __forceinline__ void ldsm_x4(unsigned& r0, unsigned& r1,
                                        unsigned& r2, unsigned& r3, unsigned a) {
    asm volatile("ldmatrix.sync.aligned.m8n8.x4.shared.b16 {%0,%1,%2,%3}, [%4];"
                 : "=r"(r0), "=r"(r1), "=r"(r2), "=r"(r3) : "r"(a));
}
__device__ __forceinline__ void ldsm_x4t(unsigned& r0, unsigned& r1,
                                         unsigned& r2, unsigned& r3, unsigned a) {
    asm volatile("ldmatrix.sync.aligned.m8n8.x4.trans.shared.b16 {%0,%1,%2,%3}, [%4];"
                 : "=r"(r0), "=r"(r1), "=r"(r2), "=r"(r3) : "r"(a));
}
__device__ __forceinline__ void mma16816(float* c, const unsigned* a,
                                         const unsigned* b) {
    asm volatile("mma.sync.aligned.m16n8k16.row.col.f32.f16.f16.f32 "
                 "{%0,%1,%2,%3}, {%4,%5,%6,%7}, {%8,%9}, {%0,%1,%2,%3};"
                 : "+f"(c[0]), "+f"(c[1]), "+f"(c[2]), "+f"(c[3])
                 : "r"(a[0]), "r"(a[1]), "r"(a[2]), "r"(a[3]),
                   "r"(b[0]), "r"(b[1]));
}

// GEMM mainloop body; smem tiles populated; stores fp16 C for 64 rows at m0.
__device__ __forceinline__ void gemm_compute(unsigned char* s_a,
                                             unsigned char* s_w,
                                             __half2* __restrict__ C,
                                             int M, int m0, int tid) {
    const int lane = tid & 31;
    const int wid = tid >> 5;
    const int wm = wid >> 2, wn = wid & 3;
    unsigned sa = (unsigned)__cvta_generic_to_shared(s_a);
    unsigned sw = (unsigned)__cvta_generic_to_shared(s_w);

    float acc[2][4][4];
#pragma unroll
    for (int mt = 0; mt < 2; mt++)
#pragma unroll
        for (int nt = 0; nt < 4; nt++)
#pragma unroll
            for (int j = 0; j < 4; j++) acc[mt][nt][j] = 0.0f;

    const int a_r0 = wm * 32 + (lane & 15);
    const int a_kh = (lane >> 4) * 8;
    const int b_kr = (lane & 7) + ((lane >> 3) & 1) * 8;
    const int b_n0 = wn * 32 + (lane >> 4) * 8;

#pragma unroll
    for (int ks = 0; ks < 8; ks++) {
        unsigned a[2][4], b[4][2];
#pragma unroll
        for (int mt = 0; mt < 2; mt++) {
            int row = a_r0 + mt * 16;
            unsigned byte = (unsigned)(row * 256 + (ks * 16 + a_kh) * 2);
            unsigned ad = sa + (byte ^ ((unsigned)(row & 7) << 4));
            ldsm_x4(a[mt][0], a[mt][1], a[mt][2], a[mt][3], ad);
        }
#pragma unroll
        for (int p = 0; p < 2; p++) {
            int k = ks * 16 + b_kr;
            unsigned byte = (unsigned)(k * 256 + (b_n0 + p * 16) * 2);
            unsigned ad = sw + (byte ^ ((unsigned)(k & 7) << 4));
            ldsm_x4t(b[2 * p][0], b[2 * p][1], b[2 * p + 1][0], b[2 * p + 1][1], ad);
        }
#pragma unroll
        for (int mt = 0; mt < 2; mt++)
#pragma unroll
            for (int nt = 0; nt < 4; nt++)
                mma16816(acc[mt][nt], a[mt], b[nt]);
    }

#pragma unroll
    for (int mt = 0; mt < 2; mt++) {
        int r0 = m0 + wm * 32 + mt * 16 + (lane >> 2);
#pragma unroll
        for (int nt = 0; nt < 4; nt++) {
            int ci = wn * 16 + nt * 4 + (lane & 3);
            if (r0 < M)
                C[(size_t)r0 * 64 + ci] = __floats2half2_rn(acc[mt][nt][0], acc[mt][nt][1]);
            if (r0 + 8 < M)
                C[(size_t)(r0 + 8) * 64 + ci] = __floats2half2_rn(acc[mt][nt][2], acc[mt][nt][3]);
        }
    }
}

__device__ __forceinline__ void load_w_tile(unsigned char* s_w,
                                            const float* __restrict__ W, int tid) {
#pragma unroll
    for (int i = 0; i < 16; i++) {
        int f = i * 256 + tid;
        int r = f >> 5, c4 = f & 31;
        float4 v = *(const float4*)&W[(size_t)r * 128 + c4 * 4];
        __half2 h0 = __floats2half2_rn(v.x, v.y);
        __half2 h1 = __floats2half2_rn(v.z, v.w);
        unsigned byte = (unsigned)(r * 256 + c4 * 8);
        unsigned swb = byte ^ ((unsigned)(r & 7) << 4);
        uint2 u = make_uint2(*(unsigned*)&h0, *(unsigned*)&h1);
        *(uint2*)(s_w + swb) = u;
    }
}

// ---------------- fused: layer-1 GEMM  ||  edge histogram / conversion ------
__global__ void __launch_bounds__(256) k_gemm1_hist(
    const float* __restrict__ x, const float* __restrict__ W1,
    __half2* __restrict__ C,
    const void* ei, const void* batch, const float* __restrict__ ew) {
    __shared__ __align__(16) unsigned char s_a[64 * 256];   // 16 KB
    __shared__ __align__(16) unsigned char s_w[128 * 256];  // 32 KB
    const int tid = threadIdx.x;

    if (blockIdx.x < GB) {
        const int m0 = blockIdx.x * 64;
#pragma unroll
        for (int i = 0; i < 8; i++) {
            int f = i * 256 + tid;
            int r = f >> 5, c4 = f & 31;
            int gm = m0 + r;
            float4 v = make_float4(0.f, 0.f, 0.f, 0.f);
            if (gm < N_NODES) v = *(const float4*)&x[(size_t)gm * 128 + c4 * 4];
            __half2 h0 = __floats2half2_rn(v.x, v.y);
            __half2 h1 = __floats2half2_rn(v.z, v.w);
            unsigned byte = (unsigned)(r * 256 + c4 * 8);
            unsigned swb = byte ^ ((unsigned)(r & 7) << 4);
            uint2 u = make_uint2(*(unsigned*)&h0, *(unsigned*)&h1);
            *(uint2*)(s_a + swb) = u;
        }
        load_w_tile(s_w, W1, tid);
        __syncthreads();
        gemm_compute(s_a, s_w, C, N_NODES, m0, tid);
        return;
    }

    // ---- histogram branch ----
    const unsigned* u32 = (const unsigned*)ei;
    int is64 = 1;
#pragma unroll
    for (int i = 1; i < 16; i += 2)
        if (u32[i] != 0u) is64 = 0;

    int t = (blockIdx.x - GB) * 256 + tid;
    int e0 = t * 2;
    if (e0 < N_EDGES) {
        int s0, s1, d0, d1;
        if (is64) {
            const longlong2* p = (const longlong2*)ei;
            longlong2 vs = __ldg(&p[t]);
            longlong2 vd = __ldg(&p[N_EDGES / 2 + t]);
            s0 = (int)vs.x; s1 = (int)vs.y;
            d0 = (int)vd.x; d1 = (int)vd.y;
        } else {
            const int2* p = (const int2*)ei;
            int2 vs = __ldg(&p[t]);
            int2 vd = __ldg(&p[N_EDGES / 2 + t]);
            s0 = vs.x; s1 = vs.y;
            d0 = vd.x; d1 = vd.y;
        }
        float2 w = __ldg(&((const float2*)ew)[t]);
        *(int2*)&g_src[e0] = make_int2(s0, s1);
        *(int2*)&g_dst[e0] = make_int2(d0, d1);
        unsigned long long f0 =
            (1ull << 44) | (unsigned long long)__float2uint_rn(w.x * 16777216.0f);
        unsigned long long f1 =
            (1ull << 44) | (unsigned long long)__float2uint_rn(w.y * 16777216.0f);
        unsigned long long o0 = atomicAdd(&g_degcnt[d0], f0);
        unsigned long long o1 = atomicAdd(&g_degcnt[d1], f1);
        g_rank[e0 + 0] = (unsigned short)(o0 >> 44);
        g_rank[e0 + 1] = (unsigned short)(o1 >> 44);
    }
    if (t < N_NODES) {
        int b = is64 ? (int)((const long long*)batch)[t]
                     : ((const int*)batch)[t];
        g_batch[t] = b;
        atomicAdd(&g_gcnt[b], 1.0f);
    }
}

// ---- 2-stage scan: unpack (cnt,deg) (+re-zero degcnt), sums, then scan -----
__global__ void __launch_bounds__(256) k_scan1() {
    __shared__ int ws[8];
    int tid = threadIdx.x;
    int t = blockIdx.x * 256 + tid;
    int c = 0;
    if (t < N_NODES) {
        unsigned long long p = g_degcnt[t];
        g_degcnt[t] = 0ull;   // restore zero invariant for next call
        c = (int)(p >> 44);
        float deg = (float)(p & ((1ull << 44) - 1ull)) * (1.0f / 16777216.0f)
                    + 1.0f;   // + self-loop
        float r = rsqrtf(deg);
        g_dinv[t] = r;
        g_self[t] = r * r;
        g_cnt[t] = c;
    }
    int v = c;
#pragma unroll
    for (int off = 16; off; off >>= 1)
        v += __shfl_down_sync(0xffffffffu, v, off);
    if ((tid & 31) == 0) ws[tid >> 5] = v;
    __syncthreads();
    if (tid == 0) {
        int s = 0;
#pragma unroll
        for (int i = 0; i < 8; i++) s += ws[i];
        g_bsum[blockIdx.x] = s;
    }
}

__global__ void __launch_bounds__(256) k_scan2() {
    __shared__ int sb[256];
    __shared__ int sh[256];
    int tid = threadIdx.x;
    int bv = (tid < NB) ? g_bsum[tid] : 0;
    sb[tid] = bv;
    __syncthreads();
#pragma unroll
    for (int off = 1; off < 256; off <<= 1) {
        int u = (tid >= off) ? sb[tid - off] : 0;
        __syncthreads();
        sb[tid] += u;
        __syncthreads();
    }
    int base = (blockIdx.x > 0) ? sb[blockIdx.x - 1] : 0;

    int t = blockIdx.x * 256 + tid;
    int c = (t < N_NODES) ? g_cnt[t] : 0;
    sh[tid] = c;
    __syncthreads();
#pragma unroll
    for (int off = 1; off < 256; off <<= 1) {
        int u = (tid >= off) ? sh[tid - off] : 0;
        __syncthreads();
        sh[tid] += u;
        __syncthreads();
    }
    if (t < N_NODES) {
        g_rowptr[t] = base + sh[tid] - c;
        if (t == N_NODES - 1) g_rowptr[N_NODES] = base + sh[tid];
    }
}

// fill CSR: atomic-free, separate arrays (measured-best for the aggregate).
// coef = dinv[src]*w  — dinv[dst] is applied per-row in the aggregate, so
// fill drops one gather per edge. 2 edges/thread.
__global__ void k_fill(const float* __restrict__ ew) {
    int t = blockIdx.x * blockDim.x + threadIdx.x;
    int e0 = t * 2;
    if (e0 >= N_EDGES) return;
    int2 s = *(const int2*)&g_src[e0];
    int2 d = *(const int2*)&g_dst[e0];
    float2 w = __ldg(&((const float2*)ew)[t]);
    int r0 = (int)g_rank[e0 + 0];
    int r1 = (int)g_rank[e0 + 1];
    int p0 = __ldg(&g_rowptr[d.x]) + r0;
    int p1 = __ldg(&g_rowptr[d.y]) + r1;
    g_csr_src[p0]  = s.x;
    g_csr_coef[p0] = g_dinv[s.x] * w.x;
    g_csr_src[p1]  = s.y;
    g_csr_coef[p1] = g_dinv[s.y] * w.y;
}

// ---------------- GEMM for fp16 input (layers 2/3, relu fused on load) ------
__global__ void __launch_bounds__(256) k_gemm_h(const uint4* __restrict__ A,
                                                const float* __restrict__ W,
                                                __half2* __restrict__ C) {
    __shared__ __align__(16) unsigned char s_a[64 * 256];   // 16 KB
    __shared__ __align__(16) unsigned char s_w[128 * 256];  // 32 KB
    const int tid = threadIdx.x;
    const int m0 = blockIdx.x * 64;

#pragma unroll
    for (int i = 0; i < 4; i++) {
        int f = i * 256 + tid;
        int r = f >> 4, u = f & 15;
        int gm = m0 + r;
        uint4 v = make_uint4(0u, 0u, 0u, 0u);
        if (gm < N_NODES) v = __ldg(&A[(size_t)gm * 16 + u]);
        __half2 z = __float2half2_rn(0.0f);
        *(__half2*)&v.x = __hmax2(*(__half2*)&v.x, z);
        *(__half2*)&v.y = __hmax2(*(__half2*)&v.y, z);
        *(__half2*)&v.z = __hmax2(*(__half2*)&v.z, z);
        *(__half2*)&v.w = __hmax2(*(__half2*)&v.w, z);
        unsigned byte = (unsigned)(r * 256 + u * 16);
        unsigned swb = byte ^ ((unsigned)(r & 7) << 4);
        *(uint4*)(s_a + swb) = v;
    }
    load_w_tile(s_w, W, tid);
    __syncthreads();
    gemm_compute(s_a, s_w, C, N_NODES, m0, tid);
}

// ---------------- aggregate: b + self[n]*hw[n] + dinv[n]*sum coef*hw[src] ---
// Separate (src, coef) arrays, fp16 feature gather (256B/row), fp32
// accumulate, 4-wide interleaved scalar MLP (measured best). Warp per node.
__device__ __forceinline__ float4 agg_node(const uint2* __restrict__ hw4,
                                           const float* __restrict__ bias,
                                           int node, int lane) {
    int r0 = __ldg(&g_rowptr[node]);
    int r1 = __ldg(&g_rowptr[node + 1]);

    float4 a0 = make_float4(0.f, 0.f, 0.f, 0.f);
    float4 a1 = a0, a2 = a0, a3 = a0;

    int e = r0;
    for (; e + 4 <= r1; e += 4) {
        int   i0 = __ldg(&g_csr_src[e + 0]);
        int   i1 = __ldg(&g_csr_src[e + 1]);
        int   i2 = __ldg(&g_csr_src[e + 2]);
        int   i3 = __ldg(&g_csr_src[e + 3]);
        float c0 = __ldg(&g_csr_coef[e + 0]);
        float c1 = __ldg(&g_csr_coef[e + 1]);
        float c2 = __ldg(&g_csr_coef[e + 2]);
        float c3 = __ldg(&g_csr_coef[e + 3]);
        uint2 u0 = __ldg(&hw4[(size_t)i0 * 32 + lane]);
        uint2 u1 = __ldg(&hw4[(size_t)i1 * 32 + lane]);
        uint2 u2 = __ldg(&hw4[(size_t)i2 * 32 + lane]);
        uint2 u3 = __ldg(&hw4[(size_t)i3 * 32 + lane]);
        float2 p, q;
        p = __half22float2(*(__half2*)&u0.x); q = __half22float2(*(__half2*)&u0.y);
        a0.x += c0 * p.x; a0.y += c0 * p.y; a0.z += c0 * q.x; a0.w += c0 * q.y;
        p = __half22float2(*(__half2*)&u1.x); q = __half22float2(*(__half2*)&u1.y);
        a1.x += c1 * p.x; a1.y += c1 * p.y; a1.z += c1 * q.x; a1.w += c1 * q.y;
        p = __half22float2(*(__half2*)&u2.x); q = __half22float2(*(__half2*)&u2.y);
        a2.x += c2 * p.x; a2.y += c2 * p.y; a2.z += c2 * q.x; a2.w += c2 * q.y;
        p = __half22float2(*(__half2*)&u3.x); q = __half22float2(*(__half2*)&u3.y);
        a3.x += c3 * p.x; a3.y += c3 * p.y; a3.z += c3 * q.x; a3.w += c3 * q.y;
    }
    for (; e < r1; e++) {
        int   i0 = __ldg(&g_csr_src[e]);
        float c0 = __ldg(&g_csr_coef[e]);
        uint2 u0 = __ldg(&hw4[(size_t)i0 * 32 + lane]);
        float2 p = __half22float2(*(__half2*)&u0.x);
        float2 q = __half22float2(*(__half2*)&u0.y);
        a0.x += c0 * p.x; a0.y += c0 * p.y; a0.z += c0 * q.x; a0.w += c0 * q.y;
    }

    // epilogue: bias + self-loop + row-uniform dinv[d] scale of the edge sum
    float4 b = *(const float4*)&bias[lane * 4];
    float  s = g_self[node];
    float  dv = g_dinv[node];
    uint2 uself = __ldg(&hw4[(size_t)node * 32 + lane]);
    float2 s0 = __half22float2(*(__half2*)&uself.x);
    float2 s1 = __half22float2(*(__half2*)&uself.y);
    return make_float4(
        b.x + s * s0.x + dv * (a0.x + a1.x + a2.x + a3.x),
        b.y + s * s0.y + dv * (a0.y + a1.y + a2.y + a3.y),
        b.z + s * s1.x + dv * (a0.z + a1.z + a2.z + a3.z),
        b.w + s * s1.y + dv * (a0.w + a1.w + a2.w + a3.w));
}

// layers 1-2: store raw (pre-relu) fp16 features; next GEMM applies relu.
__global__ void __launch_bounds__(256) k_aggregate_h(const __half2* __restrict__ hw,
                                                     const float* __restrict__ bias,
                                                     uint2* __restrict__ out) {
    int node = (blockIdx.x * 256 + threadIdx.x) >> 5;
    int lane = threadIdx.x & 31;
    if (node >= N_NODES) return;
    float4 o = agg_node((const uint2*)hw, bias, node, lane);
    uint2 r;
    __half2 h0 = __floats2half2_rn(o.x, o.y);
    __half2 h1 = __floats2half2_rn(o.z, o.w);
    r.x = *(unsigned*)&h0;
    r.y = *(unsigned*)&h1;
    out[(size_t)node * 32 + lane] = r;
}

// layer-3 aggregate fused with mean-pool accumulation
__global__ void __launch_bounds__(256) k_aggregate_pool(const __half2* __restrict__ hw,
                                                        const float* __restrict__ bias) {
    int node = (blockIdx.x * 256 + threadIdx.x) >> 5;
    int lane = threadIdx.x & 31;
    if (node >= N_NODES) return;
    float4 o = agg_node((const uint2*)hw, bias, node, lane);
    int g = g_batch[node];
    float* p = &g_emb[g * 128 + lane * 4];
    asm volatile("red.global.add.v4.f32 [%0], {%1, %2, %3, %4};"
                 :: "l"(p), "f"(o.x), "f"(o.y), "f"(o.z), "f"(o.w)
                 : "memory");
}

// ---------------- classifier (re-zeros emb/gcnt after use) ------------------
__global__ void k_classify(const float* __restrict__ lw1,
                           const float* __restrict__ lb1,
                           const float* __restrict__ lw2,
                           const float* __restrict__ lb2,
                           float* __restrict__ out) {
    int lane = threadIdx.x & 31;
    int g = (blockIdx.x * blockDim.x + threadIdx.x) >> 5;
    if (g >= N_GRAPHS) return;
    float inv = 1.0f / fmaxf(g_gcnt[g], 1.0f);
    float e[4];
#pragma unroll
    for (int j = 0; j < 4; j++) {
        e[j] = g_emb[g * 128 + lane + 32 * j] * inv;
        g_emb[g * 128 + lane + 32 * j] = 0.0f;   // restore zero invariant
    }
    if (lane == 0) g_gcnt[g] = 0.0f;             // restore zero invariant
    float t[4] = {lb1[lane], lb1[lane + 32], lb1[lane + 64], lb1[lane + 96]};
#pragma unroll
    for (int k0 = 0; k0 < 4; k0++) {
#pragma unroll
        for (int kk = 0; kk < 32; kk++) {
            float a = __shfl_sync(0xffffffffu, e[k0], kk);
            int k = k0 * 32 + kk;
            t[0] += a * lw1[k * 128 + lane];
            t[1] += a * lw1[k * 128 + lane + 32];
            t[2] += a * lw1[k * 128 + lane + 64];
            t[3] += a * lw1[k * 128 + lane + 96];
        }
    }
#pragma unroll
    for (int o = 0; o < 10; o++) {
        float p = t[0] * lw2[lane * 10 + o] + t[1] * lw2[(lane + 32) * 10 + o] +
                  t[2] * lw2[(lane + 64) * 10 + o] + t[3] * lw2[(lane + 96) * 10 + o];
#pragma unroll
        for (int off = 16; off; off >>= 1)
            p += __shfl_down_sync(0xffffffffu, p, off);
        if (lane == 0) out[g * 10 + o] = p + lb2[o];
    }
}

// ---------------- launch ----------------------------------------------------
extern "C" void kernel_launch(void* const* d_in, const int* in_sizes, int n_in,
                              void* d_out, int out_size) {
    const float* x   = (const float*)d_in[0];
    const void*  ei  = d_in[1];
    const float* ew  = (const float*)d_in[2];
    const void*  bt  = d_in[3];
    const float* W1  = (const float*)d_in[4];
    const float* b1  = (const float*)d_in[5];
    const float* W2  = (const float*)d_in[6];
    const float* b2  = (const float*)d_in[7];
    const float* W3  = (const float*)d_in[8];
    const float* b3  = (const float*)d_in[9];
    const float* lw1 = (const float*)d_in[10];
    const float* lb1 = (const float*)d_in[11];
    const float* lw2 = (const float*)d_in[12];
    const float* lb2 = (const float*)d_in[13];
    float* out = (float*)d_out;

    __half2 *bufH, *bufX;
    cudaGetSymbolAddress((void**)&bufH, g_bufH);
    cudaGetSymbolAddress((void**)&bufX, g_bufX);

    const int AB = (N_NODES * 32 + 255) / 256;   // 6250 (warp per node)

    // ---- fused layer-1 GEMM || edge histogram; then CSR build ----
    k_gemm1_hist<<<GB + EB2, 256>>>(x, W1, bufH, ei, bt, ew);
    k_scan1<<<NB, 256>>>();
    k_scan2<<<NB, 256>>>();
    k_fill<<<EB2, 256>>>(ew);

    // ---- layer 1 aggregate -> X (fp16, pre-relu) ----
    k_aggregate_h<<<AB, 256>>>(bufH, b1, (uint2*)bufX);
    // ---- layer 2: relu(X) fp16 -> H; aggregate -> X ----
    k_gemm_h<<<GB, 256>>>((const uint4*)bufX, W2, bufH);
    k_aggregate_h<<<AB, 256>>>(bufH, b2, (uint2*)bufX);
    // ---- layer 3: relu(X) fp16 -> H; aggregate + pool fused ----
    k_gemm_h<<<GB, 256>>>((const uint4*)bufX, W3, bufH);
    k_aggregate_pool<<<AB, 256>>>(bufH, b3);

    // ---- classify ----
    k_classify<<<(N_GRAPHS * 32 + 255) / 256, 256>>>(lw1, lb1, lw2, lb2, out);
}

// round 14
// speedup vs baseline: 1.1055x; 1.0229x over previous
#include <cuda_runtime.h>
#include <cuda_fp16.h>

#define N_NODES 50000
#define N_EDGES 1600000
#define N_GRAPHS 256
#define HID 128
#define NB 196    // ceil(N_NODES/256)
#define GB 782    // ceil(N_NODES/64)   (GEMM blocks)
#define EB2 3125  // N_EDGES/2/256      (hist blocks, 2 edges/thread)
#define EB4 1563  // ceil(N_EDGES/4/256) (fill blocks, 4 edges/thread)

// ---------------- scratch (static device globals; no runtime alloc) --------
// Zero-initialized at module load. Kernels restore the zero invariant for
// g_degcnt / g_emb / g_gcnt after consuming them, so every call sees zeros.
__device__ __half2 g_bufH[(size_t)N_NODES * HID / 2];  // fp16 h@W (GEMM out)
__device__ __half2 g_bufX[(size_t)N_NODES * HID / 2];  // fp16 node features
__device__ int   g_src[N_EDGES];
__device__ int   g_dst[N_EDGES];
__device__ unsigned short g_rank[N_EDGES];   // edge rank within its dst row
__device__ int   g_csr_src[N_EDGES];         // separate arrays: measured-best
__device__ float g_csr_coef[N_EDGES];        // dinv[s]*dinv[d]*w (R11 numerics)
__device__ unsigned long long g_degcnt[N_NODES]; // cnt<<44 | deg(fixed 2^-24)
__device__ int   g_cnt[N_NODES];
__device__ int   g_rowptr[N_NODES + 1];
__device__ int2  g_nodeinfo[N_NODES];        // (rowptr, dinv-as-bits) for fill
__device__ int   g_batch[N_NODES];
__device__ float g_dinv[N_NODES];
__device__ float g_self[N_NODES];
__device__ float g_emb[N_GRAPHS * HID];
__device__ float g_gcnt[N_GRAPHS];
__device__ int   g_bsum[256];

// ---------------- MMA helpers ------------------------------------------------
__device__ __forceinline__ void ldsm_x4(unsigned& r0, unsigned& r1,
                                        unsigned& r2, unsigned& r3, unsigned a) {
    asm volatile("ldmatrix.sync.aligned.m8n8.x4.shared.b16 {%0,%1,%2,%3}, [%4];"
                 : "=r"(r0), "=r"(r1), "=r"(r2), "=r"(r3) : "r"(a));
}
__device__ __forceinline__ void ldsm_x4t(unsigned& r0, unsigned& r1,
                                         unsigned& r2, unsigned& r3, unsigned a) {
    asm volatile("ldmatrix.sync.aligned.m8n8.x4.trans.shared.b16 {%0,%1,%2,%3}, [%4];"
                 : "=r"(r0), "=r"(r1), "=r"(r2), "=r"(r3) : "r"(a));
}
__device__ __forceinline__ void mma16816(float* c, const unsigned* a,
                                         const unsigned* b) {
    asm volatile("mma.sync.aligned.m16n8k16.row.col.f32.f16.f16.f32 "
                 "{%0,%1,%2,%3}, {%4,%5,%6,%7}, {%8,%9}, {%0,%1,%2,%3};"
                 : "+f"(c[0]), "+f"(c[1]), "+f"(c[2]), "+f"(c[3])
                 : "r"(a[0]), "r"(a[1]), "r"(a[2]), "r"(a[3]),
                   "r"(b[0]), "r"(b[1]));
}

// GEMM mainloop body; smem tiles populated; stores fp16 C for 64 rows at m0.
__device__ __forceinline__ void gemm_compute(unsigned char* s_a,
                                             unsigned char* s_w,
                                             __half2* __restrict__ C,
                                             int M, int m0, int tid) {
    const int lane = tid & 31;
    const int wid = tid >> 5;
    const int wm = wid >> 2, wn = wid & 3;
    unsigned sa = (unsigned)__cvta_generic_to_shared(s_a);
    unsigned sw = (unsigned)__cvta_generic_to_shared(s_w);

    float acc[2][4][4];
#pragma unroll
    for (int mt = 0; mt < 2; mt++)
#pragma unroll
        for (int nt = 0; nt < 4; nt++)
#pragma unroll
            for (int j = 0; j < 4; j++) acc[mt][nt][j] = 0.0f;

    const int a_r0 = wm * 32 + (lane & 15);
    const int a_kh = (lane >> 4) * 8;
    const int b_kr = (lane & 7) + ((lane >> 3) & 1) * 8;
    const int b_n0 = wn * 32 + (lane >> 4) * 8;

#pragma unroll
    for (int ks = 0; ks < 8; ks++) {
        unsigned a[2][4], b[4][2];
#pragma unroll
        for (int mt = 0; mt < 2; mt++) {
            int row = a_r0 + mt * 16;
            unsigned byte = (unsigned)(row * 256 + (ks * 16 + a_kh) * 2);
            unsigned ad = sa + (byte ^ ((unsigned)(row & 7) << 4));
            ldsm_x4(a[mt][0], a[mt][1], a[mt][2], a[mt][3], ad);
        }
#pragma unroll
        for (int p = 0; p < 2; p++) {
            int k = ks * 16 + b_kr;
            unsigned byte = (unsigned)(k * 256 + (b_n0 + p * 16) * 2);
            unsigned ad = sw + (byte ^ ((unsigned)(k & 7) << 4));
            ldsm_x4t(b[2 * p][0], b[2 * p][1], b[2 * p + 1][0], b[2 * p + 1][1], ad);
        }
#pragma unroll
        for (int mt = 0; mt < 2; mt++)
#pragma unroll
            for (int nt = 0; nt < 4; nt++)
                mma16816(acc[mt][nt], a[mt], b[nt]);
    }

#pragma unroll
    for (int mt = 0; mt < 2; mt++) {
        int r0 = m0 + wm * 32 + mt * 16 + (lane >> 2);
#pragma unroll
        for (int nt = 0; nt < 4; nt++) {
            int ci = wn * 16 + nt * 4 + (lane & 3);
            if (r0 < M)
                C[(size_t)r0 * 64 + ci] = __floats2half2_rn(acc[mt][nt][0], acc[mt][nt][1]);
            if (r0 + 8 < M)
                C[(size_t)(r0 + 8) * 64 + ci] = __floats2half2_rn(acc[mt][nt][2], acc[mt][nt][3]);
        }
    }
}

__device__ __forceinline__ void load_w_tile(unsigned char* s_w,
                                            const float* __restrict__ W, int tid) {
#pragma unroll
    for (int i = 0; i < 16; i++) {
        int f = i * 256 + tid;
        int r = f >> 5, c4 = f & 31;
        float4 v = *(const float4*)&W[(size_t)r * 128 + c4 * 4];
        __half2 h0 = __floats2half2_rn(v.x, v.y);
        __half2 h1 = __floats2half2_rn(v.z, v.w);
        unsigned byte = (unsigned)(r * 256 + c4 * 8);
        unsigned swb = byte ^ ((unsigned)(r & 7) << 4);
        uint2 u = make_uint2(*(unsigned*)&h0, *(unsigned*)&h1);
        *(uint2*)(s_w + swb) = u;
    }
}

// ---------------- fused: layer-1 GEMM  ||  edge histogram / conversion ------
__global__ void __launch_bounds__(256) k_gemm1_hist(
    const float* __restrict__ x, const float* __restrict__ W1,
    __half2* __restrict__ C,
    const void* ei, const void* batch, const float* __restrict__ ew) {
    __shared__ __align__(16) unsigned char s_a[64 * 256];   // 16 KB
    __shared__ __align__(16) unsigned char s_w[128 * 256];  // 32 KB
    const int tid = threadIdx.x;

    if (blockIdx.x < GB) {
        const int m0 = blockIdx.x * 64;
#pragma unroll
        for (int i = 0; i < 8; i++) {
            int f = i * 256 + tid;
            int r = f >> 5, c4 = f & 31;
            int gm = m0 + r;
            float4 v = make_float4(0.f, 0.f, 0.f, 0.f);
            if (gm < N_NODES) v = *(const float4*)&x[(size_t)gm * 128 + c4 * 4];
            __half2 h0 = __floats2half2_rn(v.x, v.y);
            __half2 h1 = __floats2half2_rn(v.z, v.w);
            unsigned byte = (unsigned)(r * 256 + c4 * 8);
            unsigned swb = byte ^ ((unsigned)(r & 7) << 4);
            uint2 u = make_uint2(*(unsigned*)&h0, *(unsigned*)&h1);
            *(uint2*)(s_a + swb) = u;
        }
        load_w_tile(s_w, W1, tid);
        __syncthreads();
        gemm_compute(s_a, s_w, C, N_NODES, m0, tid);
        return;
    }

    // ---- histogram branch ----
    const unsigned* u32 = (const unsigned*)ei;
    int is64 = 1;
#pragma unroll
    for (int i = 1; i < 16; i += 2)
        if (u32[i] != 0u) is64 = 0;

    int t = (blockIdx.x - GB) * 256 + tid;
    int e0 = t * 2;
    if (e0 < N_EDGES) {
        int s0, s1, d0, d1;
        if (is64) {
            const longlong2* p = (const longlong2*)ei;
            longlong2 vs = __ldg(&p[t]);
            longlong2 vd = __ldg(&p[N_EDGES / 2 + t]);
            s0 = (int)vs.x; s1 = (int)vs.y;
            d0 = (int)vd.x; d1 = (int)vd.y;
        } else {
            const int2* p = (const int2*)ei;
            int2 vs = __ldg(&p[t]);
            int2 vd = __ldg(&p[N_EDGES / 2 + t]);
            s0 = vs.x; s1 = vs.y;
            d0 = vd.x; d1 = vd.y;
        }
        float2 w = __ldg(&((const float2*)ew)[t]);
        *(int2*)&g_src[e0] = make_int2(s0, s1);
        *(int2*)&g_dst[e0] = make_int2(d0, d1);
        unsigned long long f0 =
            (1ull << 44) | (unsigned long long)__float2uint_rn(w.x * 16777216.0f);
        unsigned long long f1 =
            (1ull << 44) | (unsigned long long)__float2uint_rn(w.y * 16777216.0f);
        unsigned long long o0 = atomicAdd(&g_degcnt[d0], f0);
        unsigned long long o1 = atomicAdd(&g_degcnt[d1], f1);
        g_rank[e0 + 0] = (unsigned short)(o0 >> 44);
        g_rank[e0 + 1] = (unsigned short)(o1 >> 44);
    }
    if (t < N_NODES) {
        int b = is64 ? (int)((const long long*)batch)[t]
                     : ((const int*)batch)[t];
        g_batch[t] = b;
        atomicAdd(&g_gcnt[b], 1.0f);
    }
}

// ---- 2-stage scan: unpack (cnt,deg) (+re-zero degcnt), sums, then scan -----
__global__ void __launch_bounds__(256) k_scan1() {
    __shared__ int ws[8];
    int tid = threadIdx.x;
    int t = blockIdx.x * 256 + tid;
    int c = 0;
    if (t < N_NODES) {
        unsigned long long p = g_degcnt[t];
        g_degcnt[t] = 0ull;   // restore zero invariant for next call
        c = (int)(p >> 44);
        float deg = (float)(p & ((1ull << 44) - 1ull)) * (1.0f / 16777216.0f)
                    + 1.0f;   // + self-loop
        float r = rsqrtf(deg);
        g_dinv[t] = r;
        g_self[t] = r * r;
        g_cnt[t] = c;
    }
    int v = c;
#pragma unroll
    for (int off = 16; off; off >>= 1)
        v += __shfl_down_sync(0xffffffffu, v, off);
    if ((tid & 31) == 0) ws[tid >> 5] = v;
    __syncthreads();
    if (tid == 0) {
        int s = 0;
#pragma unroll
        for (int i = 0; i < 8; i++) s += ws[i];
        g_bsum[blockIdx.x] = s;
    }
}

__global__ void __launch_bounds__(256) k_scan2() {
    __shared__ int sb[256];
    __shared__ int sh[256];
    int tid = threadIdx.x;
    int bv = (tid < NB) ? g_bsum[tid] : 0;
    sb[tid] = bv;
    __syncthreads();
#pragma unroll
    for (int off = 1; off < 256; off <<= 1) {
        int u = (tid >= off) ? sb[tid - off] : 0;
        __syncthreads();
        sb[tid] += u;
        __syncthreads();
    }
    int base = (blockIdx.x > 0) ? sb[blockIdx.x - 1] : 0;

    int t = blockIdx.x * 256 + tid;
    int c = (t < N_NODES) ? g_cnt[t] : 0;
    sh[tid] = c;
    __syncthreads();
#pragma unroll
    for (int off = 1; off < 256; off <<= 1) {
        int u = (tid >= off) ? sh[tid - off] : 0;
        __syncthreads();
        sh[tid] += u;
        __syncthreads();
    }
    if (t < N_NODES) {
        int excl = base + sh[tid] - c;
        g_rowptr[t] = excl;
        g_nodeinfo[t] = make_int2(excl, __float_as_int(g_dinv[t]));
        if (t == N_NODES - 1) g_rowptr[N_NODES] = base + sh[tid];
    }
}

// fill CSR: atomic-free, separate output arrays (measured-best for the
// aggregate). One packed (rowptr,dinv) gather per dst; 4 edges/thread for MLP.
__global__ void k_fill(const float* __restrict__ ew) {
    int t = blockIdx.x * blockDim.x + threadIdx.x;
    int e0 = t * 4;
    if (e0 >= N_EDGES) return;
    int4 s = *(const int4*)&g_src[e0];
    int4 d = *(const int4*)&g_dst[e0];
    ushort4 rk = *(const ushort4*)&g_rank[e0];
    float4 w = __ldg(&((const float4*)ew)[t]);
    int2 n0 = __ldg(&g_nodeinfo[d.x]);
    int2 n1 = __ldg(&g_nodeinfo[d.y]);
    int2 n2 = __ldg(&g_nodeinfo[d.z]);
    int2 n3 = __ldg(&g_nodeinfo[d.w]);
    float ds0 = __ldg(&g_dinv[s.x]);
    float ds1 = __ldg(&g_dinv[s.y]);
    float ds2 = __ldg(&g_dinv[s.z]);
    float ds3 = __ldg(&g_dinv[s.w]);
    int p0 = n0.x + (int)rk.x;
    int p1 = n1.x + (int)rk.y;
    int p2 = n2.x + (int)rk.z;
    int p3 = n3.x + (int)rk.w;
    g_csr_src[p0]  = s.x;
    g_csr_coef[p0] = ds0 * __int_as_float(n0.y) * w.x;
    g_csr_src[p1]  = s.y;
    g_csr_coef[p1] = ds1 * __int_as_float(n1.y) * w.y;
    g_csr_src[p2]  = s.z;
    g_csr_coef[p2] = ds2 * __int_as_float(n2.y) * w.z;
    g_csr_src[p3]  = s.w;
    g_csr_coef[p3] = ds3 * __int_as_float(n3.y) * w.w;
}

// ---------------- GEMM for fp16 input (layers 2/3, relu fused on load) ------
__global__ void __launch_bounds__(256) k_gemm_h(const uint4* __restrict__ A,
                                                const float* __restrict__ W,
                                                __half2* __restrict__ C) {
    __shared__ __align__(16) unsigned char s_a[64 * 256];   // 16 KB
    __shared__ __align__(16) unsigned char s_w[128 * 256];  // 32 KB
    const int tid = threadIdx.x;
    const int m0 = blockIdx.x * 64;

#pragma unroll
    for (int i = 0; i < 4; i++) {
        int f = i * 256 + tid;
        int r = f >> 4, u = f & 15;
        int gm = m0 + r;
        uint4 v = make_uint4(0u, 0u, 0u, 0u);
        if (gm < N_NODES) v = __ldg(&A[(size_t)gm * 16 + u]);
        __half2 z = __float2half2_rn(0.0f);
        *(__half2*)&v.x = __hmax2(*(__half2*)&v.x, z);
        *(__half2*)&v.y = __hmax2(*(__half2*)&v.y, z);
        *(__half2*)&v.z = __hmax2(*(__half2*)&v.z, z);
        *(__half2*)&v.w = __hmax2(*(__half2*)&v.w, z);
        unsigned byte = (unsigned)(r * 256 + u * 16);
        unsigned swb = byte ^ ((unsigned)(r & 7) << 4);
        *(uint4*)(s_a + swb) = v;
    }
    load_w_tile(s_w, W, tid);
    __syncthreads();
    gemm_compute(s_a, s_w, C, N_NODES, m0, tid);
}

// ---------------- aggregate: b + self[n]*hw[n] + sum coef*hw[src] ----------
// R11 exact form: separate (src, coef) arrays, coef includes dinv[d];
// fp16 gather (256B/row), fp32 accumulate, 4-wide interleaved scalar MLP.
// One warp per node.
__device__ __forceinline__ float4 agg_node(const uint2* __restrict__ hw4,
                                           const float* __restrict__ bias,
                                           int node, int lane) {
    int r0 = __ldg(&g_rowptr[node]);
    int r1 = __ldg(&g_rowptr[node + 1]);

    float4 b = *(const float4*)&bias[lane * 4];
    float  s = g_self[node];
    uint2 uself = __ldg(&hw4[(size_t)node * 32 + lane]);
    float2 s0 = __half22float2(*(__half2*)&uself.x);
    float2 s1 = __half22float2(*(__half2*)&uself.y);
    float4 a0 = make_float4(b.x + s * s0.x, b.y + s * s0.y,
                            b.z + s * s1.x, b.w + s * s1.y);
    float4 a1 = make_float4(0.f, 0.f, 0.f, 0.f);
    float4 a2 = a1, a3 = a1;

    int e = r0;
    for (; e + 4 <= r1; e += 4) {
        int   i0 = __ldg(&g_csr_src[e + 0]);
        int   i1 = __ldg(&g_csr_src[e + 1]);
        int   i2 = __ldg(&g_csr_src[e + 2]);
        int   i3 = __ldg(&g_csr_src[e + 3]);
        float c0 = __ldg(&g_csr_coef[e + 0]);
        float c1 = __ldg(&g_csr_coef[e + 1]);
        float c2 = __ldg(&g_csr_coef[e + 2]);
        float c3 = __ldg(&g_csr_coef[e + 3]);
        uint2 u0 = __ldg(&hw4[(size_t)i0 * 32 + lane]);
        uint2 u1 = __ldg(&hw4[(size_t)i1 * 32 + lane]);
        uint2 u2 = __ldg(&hw4[(size_t)i2 * 32 + lane]);
        uint2 u3 = __ldg(&hw4[(size_t)i3 * 32 + lane]);
        float2 p, q;
        p = __half22float2(*(__half2*)&u0.x); q = __half22float2(*(__half2*)&u0.y);
        a0.x += c0 * p.x; a0.y += c0 * p.y; a0.z += c0 * q.x; a0.w += c0 * q.y;
        p = __half22float2(*(__half2*)&u1.x); q = __half22float2(*(__half2*)&u1.y);
        a1.x += c1 * p.x; a1.y += c1 * p.y; a1.z += c1 * q.x; a1.w += c1 * q.y;
        p = __half22float2(*(__half2*)&u2.x); q = __half22float2(*(__half2*)&u2.y);
        a2.x += c2 * p.x; a2.y += c2 * p.y; a2.z += c2 * q.x; a2.w += c2 * q.y;
        p = __half22float2(*(__half2*)&u3.x); q = __half22float2(*(__half2*)&u3.y);
        a3.x += c3 * p.x; a3.y += c3 * p.y; a3.z += c3 * q.x; a3.w += c3 * q.y;
    }
    for (; e < r1; e++) {
        int   i0 = __ldg(&g_csr_src[e]);
        float c0 = __ldg(&g_csr_coef[e]);
        uint2 u0 = __ldg(&hw4[(size_t)i0 * 32 + lane]);
        float2 p = __half22float2(*(__half2*)&u0.x);
        float2 q = __half22float2(*(__half2*)&u0.y);
        a0.x += c0 * p.x; a0.y += c0 * p.y; a0.z += c0 * q.x; a0.w += c0 * q.y;
    }
    return make_float4(a0.x + a1.x + a2.x + a3.x,
                       a0.y + a1.y + a2.y + a3.y,
                       a0.z + a1.z + a2.z + a3.z,
                       a0.w + a1.w + a2.w + a3.w);
}

// layers 1-2: store raw (pre-relu) fp16 features; next GEMM applies relu.
__global__ void __launch_bounds__(256) k_aggregate_h(const __half2* __restrict__ hw,
                                                     const float* __restrict__ bias,
                                                     uint2* __restrict__ out) {
    int node = (blockIdx.x * 256 + threadIdx.x) >> 5;
    int lane = threadIdx.x & 31;
    if (node >= N_NODES) return;
    float4 o = agg_node((const uint2*)hw, bias, node, lane);
    uint2 r;
    __half2 h0 = __floats2half2_rn(o.x, o.y);
    __half2 h1 = __floats2half2_rn(o.z, o.w);
    r.x = *(unsigned*)&h0;
    r.y = *(unsigned*)&h1;
    out[(size_t)node * 32 + lane] = r;
}

// layer-3 aggregate fused with mean-pool accumulation
__global__ void __launch_bounds__(256) k_aggregate_pool(const __half2* __restrict__ hw,
                                                        const float* __restrict__ bias) {
    int node = (blockIdx.x * 256 + threadIdx.x) >> 5;
    int lane = threadIdx.x & 31;
    if (node >= N_NODES) return;
    float4 o = agg_node((const uint2*)hw, bias, node, lane);
    int g = g_batch[node];
    float* p = &g_emb[g * 128 + lane * 4];
    asm volatile("red.global.add.v4.f32 [%0], {%1, %2, %3, %4};"
                 :: "l"(p), "f"(o.x), "f"(o.y), "f"(o.z), "f"(o.w)
                 : "memory");
}

// ---------------- classifier (re-zeros emb/gcnt after use) ------------------
__global__ void k_classify(const float* __restrict__ lw1,
                           const float* __restrict__ lb1,
                           const float* __restrict__ lw2,
                           const float* __restrict__ lb2,
                           float* __restrict__ out) {
    int lane = threadIdx.x & 31;
    int g = (blockIdx.x * blockDim.x + threadIdx.x) >> 5;
    if (g >= N_GRAPHS) return;
    float inv = 1.0f / fmaxf(g_gcnt[g], 1.0f);
    float e[4];
#pragma unroll
    for (int j = 0; j < 4; j++) {
        e[j] = g_emb[g * 128 + lane + 32 * j] * inv;
        g_emb[g * 128 + lane + 32 * j] = 0.0f;   // restore zero invariant
    }
    if (lane == 0) g_gcnt[g] = 0.0f;             // restore zero invariant
    float t[4] = {lb1[lane], lb1[lane + 32], lb1[lane + 64], lb1[lane + 96]};
#pragma unroll
    for (int k0 = 0; k0 < 4; k0++) {
#pragma unroll
        for (int kk = 0; kk < 32; kk++) {
            float a = __shfl_sync(0xffffffffu, e[k0], kk);
            int k = k0 * 32 + kk;
            t[0] += a * lw1[k * 128 + lane];
            t[1] += a * lw1[k * 128 + lane + 32];
            t[2] += a * lw1[k * 128 + lane + 64];
            t[3] += a * lw1[k * 128 + lane + 96];
        }
    }
#pragma unroll
    for (int o = 0; o < 10; o++) {
        float p = t[0] * lw2[lane * 10 + o] + t[1] * lw2[(lane + 32) * 10 + o] +
                  t[2] * lw2[(lane + 64) * 10 + o] + t[3] * lw2[(lane + 96) * 10 + o];
#pragma unroll
        for (int off = 16; off; off >>= 1)
            p += __shfl_down_sync(0xffffffffu, p, off);
        if (lane == 0) out[g * 10 + o] = p + lb2[o];
    }
}

// ---------------- launch ----------------------------------------------------
extern "C" void kernel_launch(void* const* d_in, const int* in_sizes, int n_in,
                              void* d_out, int out_size) {
    const float* x   = (const float*)d_in[0];
    const void*  ei  = d_in[1];
    const float* ew  = (const float*)d_in[2];
    const void*  bt  = d_in[3];
    const float* W1  = (const float*)d_in[4];
    const float* b1  = (const float*)d_in[5];
    const float* W2  = (const float*)d_in[6];
    const float* b2  = (const float*)d_in[7];
    const float* W3  = (const float*)d_in[8];
    const float* b3  = (const float*)d_in[9];
    const float* lw1 = (const float*)d_in[10];
    const float* lb1 = (const float*)d_in[11];
    const float* lw2 = (const float*)d_in[12];
    const float* lb2 = (const float*)d_in[13];
    float* out = (float*)d_out;

    __half2 *bufH, *bufX;
    cudaGetSymbolAddress((void**)&bufH, g_bufH);
    cudaGetSymbolAddress((void**)&bufX, g_bufX);

    const int AB = (N_NODES * 32 + 255) / 256;   // 6250 (warp per node)

    // ---- fused layer-1 GEMM || edge histogram; then CSR build ----
    k_gemm1_hist<<<GB + EB2, 256>>>(x, W1, bufH, ei, bt, ew);
    k_scan1<<<NB, 256>>>();
    k_scan2<<<NB, 256>>>();
    k_fill<<<EB4, 256>>>(ew);

    // ---- layer 1 aggregate -> X (fp16, pre-relu) ----
    k_aggregate_h<<<AB, 256>>>(bufH, b1, (uint2*)bufX);
    // ---- layer 2: relu(X) fp16 -> H; aggregate -> X ----
    k_gemm_h<<<GB, 256>>>((const uint4*)bufX, W2, bufH);
    k_aggregate_h<<<AB, 256>>>(bufH, b2, (uint2*)bufX);
    // ---- layer 3: relu(X) fp16 -> H; aggregate + pool fused ----
    k_gemm_h<<<GB, 256>>>((const uint4*)bufX, W3, bufH);
    k_aggregate_pool<<<AB, 256>>>(bufH, b3);

    // ---- classify ----
    k_classify<<<(N_GRAPHS * 32 + 255) / 256, 256>>>(lw1, lb1, lw2, lb2, out);
}

// round 15
// speedup vs baseline: 1.1148x; 1.0084x over previous
#include <cuda_runtime.h>
#include <cuda_fp16.h>

#define N_NODES 50000
#define N_EDGES 1600000
#define N_GRAPHS 256
#define HID 128
#define NB 196    // ceil(N_NODES/256)
#define GB 782    // ceil(N_NODES/64)   (GEMM blocks)
#define EB2 3125  // N_EDGES/2/256      (hist/fill blocks, 2 edges/thread)

// ---------------- scratch (static device globals; no runtime alloc) --------
// Zero-initialized at module load. Kernels restore the zero invariant for
// g_degcnt / g_emb / g_gcnt after consuming them, so every call sees zeros.
__device__ __half2 g_bufH[(size_t)N_NODES * HID / 2];  // fp16 h@W (GEMM out)
__device__ __half2 g_bufX[(size_t)N_NODES * HID / 2];  // fp16 node features
__device__ int   g_src[N_EDGES];
__device__ int   g_dst[N_EDGES];
__device__ unsigned short g_rank[N_EDGES];   // edge rank within its dst row
__device__ int   g_csr_src[N_EDGES];         // separate arrays: measured-best
__device__ float g_csr_coef[N_EDGES];        // dinv[s]*dinv[d]*w (R11 numerics)
__device__ unsigned long long g_degcnt[N_NODES]; // cnt<<44 | deg(fixed 2^-24)
__device__ int   g_cnt[N_NODES];
__device__ int   g_rowptr[N_NODES + 1];
__device__ int2  g_nodeinfo[N_NODES];        // (rowptr, dinv-as-bits) for fill
__device__ int   g_batch[N_NODES];
__device__ float g_dinv[N_NODES];
__device__ float g_self[N_NODES];
__device__ float g_emb[N_GRAPHS * HID];
__device__ float g_gcnt[N_GRAPHS];
__device__ int   g_bsum[256];

// ---------------- MMA helpers ------------------------------------------------
__device__ __forceinline__ void ldsm_x4(unsigned& r0, unsigned& r1,
                                        unsigned& r2, unsigned& r3, unsigned a) {
    asm volatile("ldmatrix.sync.aligned.m8n8.x4.shared.b16 {%0,%1,%2,%3}, [%4];"
                 : "=r"(r0), "=r"(r1), "=r"(r2), "=r"(r3) : "r"(a));
}
__device__ __forceinline__ void ldsm_x4t(unsigned& r0, unsigned& r1,
                                         unsigned& r2, unsigned& r3, unsigned a) {
    asm volatile("ldmatrix.sync.aligned.m8n8.x4.trans.shared.b16 {%0,%1,%2,%3}, [%4];"
                 : "=r"(r0), "=r"(r1), "=r"(r2), "=r"(r3) : "r"(a));
}
__device__ __forceinline__ void mma16816(float* c, const unsigned* a,
                                         const unsigned* b) {
    asm volatile("mma.sync.aligned.m16n8k16.row.col.f32.f16.f16.f32 "
                 "{%0,%1,%2,%3}, {%4,%5,%6,%7}, {%8,%9}, {%0,%1,%2,%3};"
                 : "+f"(c[0]), "+f"(c[1]), "+f"(c[2]), "+f"(c[3])
                 : "r"(a[0]), "r"(a[1]), "r"(a[2]), "r"(a[3]),
                   "r"(b[0]), "r"(b[1]));
}

// GEMM mainloop body; smem tiles populated; stores fp16 C for 64 rows at m0.
__device__ __forceinline__ void gemm_compute(unsigned char* s_a,
                                             unsigned char* s_w,
                                             __half2* __restrict__ C,
                                             int M, int m0, int tid) {
    const int lane = tid & 31;
    const int wid = tid >> 5;
    const int wm = wid >> 2, wn = wid & 3;
    unsigned sa = (unsigned)__cvta_generic_to_shared(s_a);
    unsigned sw = (unsigned)__cvta_generic_to_shared(s_w);

    float acc[2][4][4];
#pragma unroll
    for (int mt = 0; mt < 2; mt++)
#pragma unroll
        for (int nt = 0; nt < 4; nt++)
#pragma unroll
            for (int j = 0; j < 4; j++) acc[mt][nt][j] = 0.0f;

    const int a_r0 = wm * 32 + (lane & 15);
    const int a_kh = (lane >> 4) * 8;
    const int b_kr = (lane & 7) + ((lane >> 3) & 1) * 8;
    const int b_n0 = wn * 32 + (lane >> 4) * 8;

#pragma unroll
    for (int ks = 0; ks < 8; ks++) {
        unsigned a[2][4], b[4][2];
#pragma unroll
        for (int mt = 0; mt < 2; mt++) {
            int row = a_r0 + mt * 16;
            unsigned byte = (unsigned)(row * 256 + (ks * 16 + a_kh) * 2);
            unsigned ad = sa + (byte ^ ((unsigned)(row & 7) << 4));
            ldsm_x4(a[mt][0], a[mt][1], a[mt][2], a[mt][3], ad);
        }
#pragma unroll
        for (int p = 0; p < 2; p++) {
            int k = ks * 16 + b_kr;
            unsigned byte = (unsigned)(k * 256 + (b_n0 + p * 16) * 2);
            unsigned ad = sw + (byte ^ ((unsigned)(k & 7) << 4));
            ldsm_x4t(b[2 * p][0], b[2 * p][1], b[2 * p + 1][0], b[2 * p + 1][1], ad);
        }
#pragma unroll
        for (int mt = 0; mt < 2; mt++)
#pragma unroll
            for (int nt = 0; nt < 4; nt++)
                mma16816(acc[mt][nt], a[mt], b[nt]);
    }

#pragma unroll
    for (int mt = 0; mt < 2; mt++) {
        int r0 = m0 + wm * 32 + mt * 16 + (lane >> 2);
#pragma unroll
        for (int nt = 0; nt < 4; nt++) {
            int ci = wn * 16 + nt * 4 + (lane & 3);
            if (r0 < M)
                C[(size_t)r0 * 64 + ci] = __floats2half2_rn(acc[mt][nt][0], acc[mt][nt][1]);
            if (r0 + 8 < M)
                C[(size_t)(r0 + 8) * 64 + ci] = __floats2half2_rn(acc[mt][nt][2], acc[mt][nt][3]);
        }
    }
}

__device__ __forceinline__ void load_w_tile(unsigned char* s_w,
                                            const float* __restrict__ W, int tid) {
#pragma unroll
    for (int i = 0; i < 16; i++) {
        int f = i * 256 + tid;
        int r = f >> 5, c4 = f & 31;
        float4 v = *(const float4*)&W[(size_t)r * 128 + c4 * 4];
        __half2 h0 = __floats2half2_rn(v.x, v.y);
        __half2 h1 = __floats2half2_rn(v.z, v.w);
        unsigned byte = (unsigned)(r * 256 + c4 * 8);
        unsigned swb = byte ^ ((unsigned)(r & 7) << 4);
        uint2 u = make_uint2(*(unsigned*)&h0, *(unsigned*)&h1);
        *(uint2*)(s_w + swb) = u;
    }
}

// ---------------- fused: layer-1 GEMM  ||  edge histogram / conversion ------
__global__ void __launch_bounds__(256) k_gemm1_hist(
    const float* __restrict__ x, const float* __restrict__ W1,
    __half2* __restrict__ C,
    const void* ei, const void* batch, const float* __restrict__ ew) {
    __shared__ __align__(16) unsigned char s_a[64 * 256];   // 16 KB
    __shared__ __align__(16) unsigned char s_w[128 * 256];  // 32 KB
    const int tid = threadIdx.x;

    if (blockIdx.x < GB) {
        const int m0 = blockIdx.x * 64;
#pragma unroll
        for (int i = 0; i < 8; i++) {
            int f = i * 256 + tid;
            int r = f >> 5, c4 = f & 31;
            int gm = m0 + r;
            float4 v = make_float4(0.f, 0.f, 0.f, 0.f);
            if (gm < N_NODES) v = *(const float4*)&x[(size_t)gm * 128 + c4 * 4];
            __half2 h0 = __floats2half2_rn(v.x, v.y);
            __half2 h1 = __floats2half2_rn(v.z, v.w);
            unsigned byte = (unsigned)(r * 256 + c4 * 8);
            unsigned swb = byte ^ ((unsigned)(r & 7) << 4);
            uint2 u = make_uint2(*(unsigned*)&h0, *(unsigned*)&h1);
            *(uint2*)(s_a + swb) = u;
        }
        load_w_tile(s_w, W1, tid);
        __syncthreads();
        gemm_compute(s_a, s_w, C, N_NODES, m0, tid);
        return;
    }

    // ---- histogram branch ----
    const unsigned* u32 = (const unsigned*)ei;
    int is64 = 1;
#pragma unroll
    for (int i = 1; i < 16; i += 2)
        if (u32[i] != 0u) is64 = 0;

    int t = (blockIdx.x - GB) * 256 + tid;
    int e0 = t * 2;
    if (e0 < N_EDGES) {
        int s0, s1, d0, d1;
        if (is64) {
            const longlong2* p = (const longlong2*)ei;
            longlong2 vs = __ldg(&p[t]);
            longlong2 vd = __ldg(&p[N_EDGES / 2 + t]);
            s0 = (int)vs.x; s1 = (int)vs.y;
            d0 = (int)vd.x; d1 = (int)vd.y;
        } else {
            const int2* p = (const int2*)ei;
            int2 vs = __ldg(&p[t]);
            int2 vd = __ldg(&p[N_EDGES / 2 + t]);
            s0 = vs.x; s1 = vs.y;
            d0 = vd.x; d1 = vd.y;
        }
        float2 w = __ldg(&((const float2*)ew)[t]);
        *(int2*)&g_src[e0] = make_int2(s0, s1);
        *(int2*)&g_dst[e0] = make_int2(d0, d1);
        unsigned long long f0 =
            (1ull << 44) | (unsigned long long)__float2uint_rn(w.x * 16777216.0f);
        unsigned long long f1 =
            (1ull << 44) | (unsigned long long)__float2uint_rn(w.y * 16777216.0f);
        unsigned long long o0 = atomicAdd(&g_degcnt[d0], f0);
        unsigned long long o1 = atomicAdd(&g_degcnt[d1], f1);
        g_rank[e0 + 0] = (unsigned short)(o0 >> 44);
        g_rank[e0 + 1] = (unsigned short)(o1 >> 44);
    }
    if (t < N_NODES) {
        int b = is64 ? (int)((const long long*)batch)[t]
                     : ((const int*)batch)[t];
        g_batch[t] = b;
        atomicAdd(&g_gcnt[b], 1.0f);
    }
}

// ---- 2-stage scan: unpack (cnt,deg) (+re-zero degcnt), sums, then scan -----
__global__ void __launch_bounds__(256) k_scan1() {
    __shared__ int ws[8];
    int tid = threadIdx.x;
    int t = blockIdx.x * 256 + tid;
    int c = 0;
    if (t < N_NODES) {
        unsigned long long p = g_degcnt[t];
        g_degcnt[t] = 0ull;   // restore zero invariant for next call
        c = (int)(p >> 44);
        float deg = (float)(p & ((1ull << 44) - 1ull)) * (1.0f / 16777216.0f)
                    + 1.0f;   // + self-loop
        float r = rsqrtf(deg);
        g_dinv[t] = r;
        g_self[t] = r * r;
        g_cnt[t] = c;
    }
    int v = c;
#pragma unroll
    for (int off = 16; off; off >>= 1)
        v += __shfl_down_sync(0xffffffffu, v, off);
    if ((tid & 31) == 0) ws[tid >> 5] = v;
    __syncthreads();
    if (tid == 0) {
        int s = 0;
#pragma unroll
        for (int i = 0; i < 8; i++) s += ws[i];
        g_bsum[blockIdx.x] = s;
    }
}

__global__ void __launch_bounds__(256) k_scan2() {
    __shared__ int sb[256];
    __shared__ int sh[256];
    int tid = threadIdx.x;
    int bv = (tid < NB) ? g_bsum[tid] : 0;
    sb[tid] = bv;
    __syncthreads();
#pragma unroll
    for (int off = 1; off < 256; off <<= 1) {
        int u = (tid >= off) ? sb[tid - off] : 0;
        __syncthreads();
        sb[tid] += u;
        __syncthreads();
    }
    int base = (blockIdx.x > 0) ? sb[blockIdx.x - 1] : 0;

    int t = blockIdx.x * 256 + tid;
    int c = (t < N_NODES) ? g_cnt[t] : 0;
    sh[tid] = c;
    __syncthreads();
#pragma unroll
    for (int off = 1; off < 256; off <<= 1) {
        int u = (tid >= off) ? sh[tid - off] : 0;
        __syncthreads();
        sh[tid] += u;
        __syncthreads();
    }
    if (t < N_NODES) {
        int excl = base + sh[tid] - c;
        g_rowptr[t] = excl;
        g_nodeinfo[t] = make_int2(excl, __float_as_int(g_dinv[t]));
        if (t == N_NODES - 1) g_rowptr[N_NODES] = base + sh[tid];
    }
}

// fill CSR: atomic-free, separate output arrays (measured-best for the
// aggregate). One packed (rowptr,dinv) gather per dst + one dinv[s] gather;
// 2 edges/thread (measured-best occupancy for this store-bound kernel).
__global__ void k_fill(const float* __restrict__ ew) {
    int t = blockIdx.x * blockDim.x + threadIdx.x;
    int e0 = t * 2;
    if (e0 >= N_EDGES) return;
    int2 s = *(const int2*)&g_src[e0];
    int2 d = *(const int2*)&g_dst[e0];
    float2 w = __ldg(&((const float2*)ew)[t]);
    int r0 = (int)g_rank[e0 + 0];
    int r1 = (int)g_rank[e0 + 1];
    int2 n0 = __ldg(&g_nodeinfo[d.x]);
    int2 n1 = __ldg(&g_nodeinfo[d.y]);
    float ds0 = __ldg(&g_dinv[s.x]);
    float ds1 = __ldg(&g_dinv[s.y]);
    int p0 = n0.x + r0;
    int p1 = n1.x + r1;
    g_csr_src[p0]  = s.x;
    g_csr_coef[p0] = ds0 * __int_as_float(n0.y) * w.x;
    g_csr_src[p1]  = s.y;
    g_csr_coef[p1] = ds1 * __int_as_float(n1.y) * w.y;
}

// ---------------- GEMM for fp16 input (layers 2/3, relu fused on load) ------
__global__ void __launch_bounds__(256) k_gemm_h(const uint4* __restrict__ A,
                                                const float* __restrict__ W,
                                                __half2* __restrict__ C) {
    __shared__ __align__(16) unsigned char s_a[64 * 256];   // 16 KB
    __shared__ __align__(16) unsigned char s_w[128 * 256];  // 32 KB
    const int tid = threadIdx.x;
    const int m0 = blockIdx.x * 64;

#pragma unroll
    for (int i = 0; i < 4; i++) {
        int f = i * 256 + tid;
        int r = f >> 4, u = f & 15;
        int gm = m0 + r;
        uint4 v = make_uint4(0u, 0u, 0u, 0u);
        if (gm < N_NODES) v = __ldg(&A[(size_t)gm * 16 + u]);
        __half2 z = __float2half2_rn(0.0f);
        *(__half2*)&v.x = __hmax2(*(__half2*)&v.x, z);
        *(__half2*)&v.y = __hmax2(*(__half2*)&v.y, z);
        *(__half2*)&v.z = __hmax2(*(__half2*)&v.z, z);
        *(__half2*)&v.w = __hmax2(*(__half2*)&v.w, z);
        unsigned byte = (unsigned)(r * 256 + u * 16);
        unsigned swb = byte ^ ((unsigned)(r & 7) << 4);
        *(uint4*)(s_a + swb) = v;
    }
    load_w_tile(s_w, W, tid);
    __syncthreads();
    gemm_compute(s_a, s_w, C, N_NODES, m0, tid);
}

// ---------------- aggregate: b + self[n]*hw[n] + sum coef*hw[src] ----------
// R11 exact form: separate (src, coef) arrays, coef includes dinv[d];
// fp16 gather (256B/row), fp32 accumulate, 4-wide interleaved scalar MLP.
// One warp per node.
__device__ __forceinline__ float4 agg_node(const uint2* __restrict__ hw4,
                                           const float* __restrict__ bias,
                                           int node, int lane) {
    int r0 = __ldg(&g_rowptr[node]);
    int r1 = __ldg(&g_rowptr[node + 1]);

    float4 b = *(const float4*)&bias[lane * 4];
    float  s = g_self[node];
    uint2 uself = __ldg(&hw4[(size_t)node * 32 + lane]);
    float2 s0 = __half22float2(*(__half2*)&uself.x);
    float2 s1 = __half22float2(*(__half2*)&uself.y);
    float4 a0 = make_float4(b.x + s * s0.x, b.y + s * s0.y,
                            b.z + s * s1.x, b.w + s * s1.y);
    float4 a1 = make_float4(0.f, 0.f, 0.f, 0.f);
    float4 a2 = a1, a3 = a1;

    int e = r0;
    for (; e + 4 <= r1; e += 4) {
        int   i0 = __ldg(&g_csr_src[e + 0]);
        int   i1 = __ldg(&g_csr_src[e + 1]);
        int   i2 = __ldg(&g_csr_src[e + 2]);
        int   i3 = __ldg(&g_csr_src[e + 3]);
        float c0 = __ldg(&g_csr_coef[e + 0]);
        float c1 = __ldg(&g_csr_coef[e + 1]);
        float c2 = __ldg(&g_csr_coef[e + 2]);
        float c3 = __ldg(&g_csr_coef[e + 3]);
        uint2 u0 = __ldg(&hw4[(size_t)i0 * 32 + lane]);
        uint2 u1 = __ldg(&hw4[(size_t)i1 * 32 + lane]);
        uint2 u2 = __ldg(&hw4[(size_t)i2 * 32 + lane]);
        uint2 u3 = __ldg(&hw4[(size_t)i3 * 32 + lane]);
        float2 p, q;
        p = __half22float2(*(__half2*)&u0.x); q = __half22float2(*(__half2*)&u0.y);
        a0.x += c0 * p.x; a0.y += c0 * p.y; a0.z += c0 * q.x; a0.w += c0 * q.y;
        p = __half22float2(*(__half2*)&u1.x); q = __half22float2(*(__half2*)&u1.y);
        a1.x += c1 * p.x; a1.y += c1 * p.y; a1.z += c1 * q.x; a1.w += c1 * q.y;
        p = __half22float2(*(__half2*)&u2.x); q = __half22float2(*(__half2*)&u2.y);
        a2.x += c2 * p.x; a2.y += c2 * p.y; a2.z += c2 * q.x; a2.w += c2 * q.y;
        p = __half22float2(*(__half2*)&u3.x); q = __half22float2(*(__half2*)&u3.y);
        a3.x += c3 * p.x; a3.y += c3 * p.y; a3.z += c3 * q.x; a3.w += c3 * q.y;
    }
    for (; e < r1; e++) {
        int   i0 = __ldg(&g_csr_src[e]);
        float c0 = __ldg(&g_csr_coef[e]);
        uint2 u0 = __ldg(&hw4[(size_t)i0 * 32 + lane]);
        float2 p = __half22float2(*(__half2*)&u0.x);
        float2 q = __half22float2(*(__half2*)&u0.y);
        a0.x += c0 * p.x; a0.y += c0 * p.y; a0.z += c0 * q.x; a0.w += c0 * q.y;
    }
    return make_float4(a0.x + a1.x + a2.x + a3.x,
                       a0.y + a1.y + a2.y + a3.y,
                       a0.z + a1.z + a2.z + a3.z,
                       a0.w + a1.w + a2.w + a3.w);
}

// layers 1-2: store raw (pre-relu) fp16 features; next GEMM applies relu.
__global__ void __launch_bounds__(256) k_aggregate_h(const __half2* __restrict__ hw,
                                                     const float* __restrict__ bias,
                                                     uint2* __restrict__ out) {
    int node = (blockIdx.x * 256 + threadIdx.x) >> 5;
    int lane = threadIdx.x & 31;
    if (node >= N_NODES) return;
    float4 o = agg_node((const uint2*)hw, bias, node, lane);
    uint2 r;
    __half2 h0 = __floats2half2_rn(o.x, o.y);
    __half2 h1 = __floats2half2_rn(o.z, o.w);
    r.x = *(unsigned*)&h0;
    r.y = *(unsigned*)&h1;
    out[(size_t)node * 32 + lane] = r;
}

// layer-3 aggregate fused with mean-pool accumulation
__global__ void __launch_bounds__(256) k_aggregate_pool(const __half2* __restrict__ hw,
                                                        const float* __restrict__ bias) {
    int node = (blockIdx.x * 256 + threadIdx.x) >> 5;
    int lane = threadIdx.x & 31;
    if (node >= N_NODES) return;
    float4 o = agg_node((const uint2*)hw, bias, node, lane);
    int g = g_batch[node];
    float* p = &g_emb[g * 128 + lane * 4];
    asm volatile("red.global.add.v4.f32 [%0], {%1, %2, %3, %4};"
                 :: "l"(p), "f"(o.x), "f"(o.y), "f"(o.z), "f"(o.w)
                 : "memory");
}

// ---------------- classifier (re-zeros emb/gcnt after use) ------------------
__global__ void k_classify(const float* __restrict__ lw1,
                           const float* __restrict__ lb1,
                           const float* __restrict__ lw2,
                           const float* __restrict__ lb2,
                           float* __restrict__ out) {
    int lane = threadIdx.x & 31;
    int g = (blockIdx.x * blockDim.x + threadIdx.x) >> 5;
    if (g >= N_GRAPHS) return;
    float inv = 1.0f / fmaxf(g_gcnt[g], 1.0f);
    float e[4];
#pragma unroll
    for (int j = 0; j < 4; j++) {
        e[j] = g_emb[g * 128 + lane + 32 * j] * inv;
        g_emb[g * 128 + lane + 32 * j] = 0.0f;   // restore zero invariant
    }
    if (lane == 0) g_gcnt[g] = 0.0f;             // restore zero invariant
    float t[4] = {lb1[lane], lb1[lane + 32], lb1[lane + 64], lb1[lane + 96]};
#pragma unroll
    for (int k0 = 0; k0 < 4; k0++) {
#pragma unroll
        for (int kk = 0; kk < 32; kk++) {
            float a = __shfl_sync(0xffffffffu, e[k0], kk);
            int k = k0 * 32 + kk;
            t[0] += a * lw1[k * 128 + lane];
            t[1] += a * lw1[k * 128 + lane + 32];
            t[2] += a * lw1[k * 128 + lane + 64];
            t[3] += a * lw1[k * 128 + lane + 96];
        }
    }
#pragma unroll
    for (int o = 0; o < 10; o++) {
        float p = t[0] * lw2[lane * 10 + o] + t[1] * lw2[(lane + 32) * 10 + o] +
                  t[2] * lw2[(lane + 64) * 10 + o] + t[3] * lw2[(lane + 96) * 10 + o];
#pragma unroll
        for (int off = 16; off; off >>= 1)
            p += __shfl_down_sync(0xffffffffu, p, off);
        if (lane == 0) out[g * 10 + o] = p + lb2[o];
    }
}

// ---------------- launch ----------------------------------------------------
extern "C" void kernel_launch(void* const* d_in, const int* in_sizes, int n_in,
                              void* d_out, int out_size) {
    const float* x   = (const float*)d_in[0];
    const void*  ei  = d_in[1];
    const float* ew  = (const float*)d_in[2];
    const void*  bt  = d_in[3];
    const float* W1  = (const float*)d_in[4];
    const float* b1  = (const float*)d_in[5];
    const float* W2  = (const float*)d_in[6];
    const float* b2  = (const float*)d_in[7];
    const float* W3  = (const float*)d_in[8];
    const float* b3  = (const float*)d_in[9];
    const float* lw1 = (const float*)d_in[10];
    const float* lb1 = (const float*)d_in[11];
    const float* lw2 = (const float*)d_in[12];
    const float* lb2 = (const float*)d_in[13];
    float* out = (float*)d_out;

    __half2 *bufH, *bufX;
    cudaGetSymbolAddress((void**)&bufH, g_bufH);
    cudaGetSymbolAddress((void**)&bufX, g_bufX);

    const int AB = (N_NODES * 32 + 255) / 256;   // 6250 (warp per node)

    // ---- fused layer-1 GEMM || edge histogram; then CSR build ----
    k_gemm1_hist<<<GB + EB2, 256>>>(x, W1, bufH, ei, bt, ew);
    k_scan1<<<NB, 256>>>();
    k_scan2<<<NB, 256>>>();
    k_fill<<<EB2, 256>>>(ew);

    // ---- layer 1 aggregate -> X (fp16, pre-relu) ----
    k_aggregate_h<<<AB, 256>>>(bufH, b1, (uint2*)bufX);
    // ---- layer 2: relu(X) fp16 -> H; aggregate -> X ----
    k_gemm_h<<<GB, 256>>>((const uint4*)bufX, W2, bufH);
    k_aggregate_h<<<AB, 256>>>(bufH, b2, (uint2*)bufX);
    // ---- layer 3: relu(X) fp16 -> H; aggregate + pool fused ----
    k_gemm_h<<<GB, 256>>>((const uint4*)bufX, W3, bufH);
    k_aggregate_pool<<<AB, 256>>>(bufH, b3);

    // ---- classify ----
    k_classify<<<(N_GRAPHS * 32 + 255) / 256, 256>>>(lw1, lb1, lw2, lb2, out);
}